// round 10
// baseline (speedup 1.0000x reference)
#include <cuda_runtime.h>
#include <cuda_fp16.h>

#define D 64
#define NU_MAX 100001
#define NI_MAX 200001
#define NMAX (NU_MAX + NI_MAX)
#define PMAX 3200000
#define SCAN_BLK 1024

__device__ __forceinline__ __half2 u2h2(unsigned u) {
    __half2 h; *reinterpret_cast<unsigned*>(&h) = u; return h;
}
__device__ __forceinline__ unsigned h22u(__half2 h) {
    return *reinterpret_cast<unsigned*>(&h);
}

// Scratch (.bss, no allocation). fp16 feature rows: 64 halves = 128B.
__device__ __half g_x0[(size_t)NMAX * D];
__device__ __half g_h1[(size_t)NMAX * D];
__device__ __half g_h2[(size_t)NMAX * D];
__device__ int2   g_edge[2 * PMAX];       // {col, val_bits}; [0,P)=user CSR, [P,2P)=item CSC
__device__ int    g_u_ptr[NU_MAX + 2];
__device__ int    g_i_ptr[NI_MAX + 2];
__device__ int    g_i_work[NI_MAX + 2];
__device__ int    g_cnt[NI_MAX + 2];
__device__ int    g_bsums[512];

// ---------------------------------------------------------------------------
// init: g_x0 = half(concat(ue, ie)); zero item counters.
// ---------------------------------------------------------------------------
__global__ void init_kernel(const float4* __restrict__ ue,
                            const float4* __restrict__ ie,
                            uint4* __restrict__ x0,
                            int* __restrict__ cnt,
                            int n_user_u4, int n_total_u4, int n_cnt) {
    int i = blockIdx.x * blockDim.x + threadIdx.x;
    if (i < n_cnt) cnt[i] = 0;
    if (i >= n_total_u4) return;
    const float4* src = (i < n_user_u4) ? (ue + (size_t)i * 2)
                                        : (ie + (size_t)(i - n_user_u4) * 2);
    float4 f0 = src[0];
    float4 f1 = src[1];
    uint4 o;
    o.x = h22u(__floats2half2_rn(f0.x, f0.y));
    o.y = h22u(__floats2half2_rn(f0.z, f0.w));
    o.z = h22u(__floats2half2_rn(f1.x, f1.y));
    o.w = h22u(__floats2half2_rn(f1.z, f1.w));
    x0[i] = o;
}

// ---------------------------------------------------------------------------
// u_ptr[r] = lower_bound(row[0:P], r)
// ---------------------------------------------------------------------------
__global__ void build_uptr_kernel(const int* __restrict__ row, int P,
                                  int* __restrict__ uptr, int n_users) {
    int r = blockIdx.x * blockDim.x + threadIdx.x;
    if (r > n_users) return;
    int lo = 0, hi = P;
    while (lo < hi) {
        int mid = (lo + hi) >> 1;
        if (row[mid] < r) lo = mid + 1; else hi = mid;
    }
    uptr[r] = lo;
}

// ---------------------------------------------------------------------------
// count item degrees + pack user-block edges
// ---------------------------------------------------------------------------
__global__ void count_pack_kernel(const int* __restrict__ col,
                                  const float* __restrict__ vals, int P,
                                  int* __restrict__ cnt,
                                  int2* __restrict__ edge, int n_users) {
    int e = blockIdx.x * blockDim.x + threadIdx.x;
    if (e >= P) return;
    int c = col[e];
    atomicAdd(&cnt[c - n_users], 1);
    edge[e] = make_int2(c, __float_as_int(vals[e]));
}

// ---------------------------------------------------------------------------
// exclusive scan -> i_ptr (+P offset)
// ---------------------------------------------------------------------------
__global__ void scan1_kernel(const int* __restrict__ cnt, int* __restrict__ ptr,
                             int* __restrict__ bsums, int n) {
    __shared__ int sh[SCAN_BLK];
    int i = blockIdx.x * SCAN_BLK + threadIdx.x;
    int v = (i < n) ? cnt[i] : 0;
    sh[threadIdx.x] = v;
    __syncthreads();
    for (int off = 1; off < SCAN_BLK; off <<= 1) {
        int t = 0;
        if ((int)threadIdx.x >= off) t = sh[threadIdx.x - off];
        __syncthreads();
        sh[threadIdx.x] += t;
        __syncthreads();
    }
    if (i < n) ptr[i] = sh[threadIdx.x] - v;
    if (threadIdx.x == SCAN_BLK - 1) bsums[blockIdx.x] = sh[SCAN_BLK - 1];
}

__global__ void scan2_kernel(int* __restrict__ bsums, int nb) {
    __shared__ int sh[512];
    int v = ((int)threadIdx.x < nb) ? bsums[threadIdx.x] : 0;
    sh[threadIdx.x] = v;
    __syncthreads();
    for (int off = 1; off < 512; off <<= 1) {
        int t = 0;
        if ((int)threadIdx.x >= off) t = sh[threadIdx.x - off];
        __syncthreads();
        sh[threadIdx.x] += t;
        __syncthreads();
    }
    if ((int)threadIdx.x < nb) bsums[threadIdx.x] = sh[threadIdx.x] - v;
}

__global__ void scan3_kernel(int* __restrict__ ptr, int* __restrict__ work,
                             const int* __restrict__ bsums, int n, int offset) {
    int i = blockIdx.x * blockDim.x + threadIdx.x;
    if (i >= n) return;
    int p = ptr[i] + bsums[i >> 10] + offset;
    ptr[i] = p;
    work[i] = p;
}

// ---------------------------------------------------------------------------
// scatter transpose (item CSC), single 8B store
// ---------------------------------------------------------------------------
__global__ void scatter_kernel(const int* __restrict__ row,
                               const int* __restrict__ col,
                               const float* __restrict__ vals, int P,
                               int* __restrict__ iwork,
                               int2* __restrict__ edge, int n_users) {
    int e = blockIdx.x * blockDim.x + threadIdx.x;
    if (e >= P) return;
    int it = col[e] - n_users;
    int pos = atomicAdd(&iwork[it], 1);   // already offset by P
    edge[pos] = make_int2(row[e], __float_as_int(vals[e]));
}

// ---------------------------------------------------------------------------
// Joint-row SpMM: warp processes 4 rows SEQUENTIALLY; the 4 lane-groups take
// every-4th edge of the same row (trip count = ceil(deg/4), warp-uniform).
// lane = (egrp<<3)|chunk; chunk owns 16B (8 halves) of the 128B fp16 row.
// Cross-group reduction: 2 shfl_down steps -> lanes 0..7 hold the full row.
// ---------------------------------------------------------------------------
#define GATHER_FMA(idx_)  {                                                  \
    int c_ = (idx_) < e ? (idx_) : s;                                        \
    int2 p_ = edge[c_];                                                      \
    float v_ = (idx_) < e ? __int_as_float(p_.y) : 0.f;                      \
    uint4 u_ = x[(size_t)p_.x * 8 + chunk];                                  \
    float2 f0_ = __half22float2(u2h2(u_.x));                                 \
    float2 f1_ = __half22float2(u2h2(u_.y));                                 \
    float2 f2_ = __half22float2(u2h2(u_.z));                                 \
    float2 f3_ = __half22float2(u2h2(u_.w));                                 \
    a0 = fmaf(v_, f0_.x, a0); a1 = fmaf(v_, f0_.y, a1);                      \
    a2 = fmaf(v_, f1_.x, a2); a3 = fmaf(v_, f1_.y, a3);                      \
    a4 = fmaf(v_, f2_.x, a4); a5 = fmaf(v_, f2_.y, a5);                      \
    a6 = fmaf(v_, f3_.x, a6); a7 = fmaf(v_, f3_.y, a7); }

#define REDUCE8() {                                                          \
    a0 += __shfl_down_sync(0xffffffffu, a0, 8);                              \
    a1 += __shfl_down_sync(0xffffffffu, a1, 8);                              \
    a2 += __shfl_down_sync(0xffffffffu, a2, 8);                              \
    a3 += __shfl_down_sync(0xffffffffu, a3, 8);                              \
    a4 += __shfl_down_sync(0xffffffffu, a4, 8);                              \
    a5 += __shfl_down_sync(0xffffffffu, a5, 8);                              \
    a6 += __shfl_down_sync(0xffffffffu, a6, 8);                              \
    a7 += __shfl_down_sync(0xffffffffu, a7, 8);                              \
    a0 += __shfl_down_sync(0xffffffffu, a0, 16);                             \
    a1 += __shfl_down_sync(0xffffffffu, a1, 16);                             \
    a2 += __shfl_down_sync(0xffffffffu, a2, 16);                             \
    a3 += __shfl_down_sync(0xffffffffu, a3, 16);                             \
    a4 += __shfl_down_sync(0xffffffffu, a4, 16);                             \
    a5 += __shfl_down_sync(0xffffffffu, a5, 16);                             \
    a6 += __shfl_down_sync(0xffffffffu, a6, 16);                             \
    a7 += __shfl_down_sync(0xffffffffu, a7, 16); }

__global__ void spmm_kernel(const uint4* __restrict__ x,
                            uint4* __restrict__ y,
                            const int2* __restrict__ edge,
                            const int* __restrict__ uptr,
                            const int* __restrict__ iptr,
                            int n_users, int n_total) {
    int warp = (blockIdx.x * blockDim.x + threadIdx.x) >> 5;
    int lane = threadIdx.x & 31;
    int egrp = lane >> 3;
    int chunk = lane & 7;
    int r0 = warp << 2;
    if (r0 >= n_total) return;

    #pragma unroll
    for (int j = 0; j < 4; j++) {
        int r = r0 + j;
        if (r >= n_total) break;
        int s, e;
        if (r < n_users) { s = uptr[r]; e = uptr[r + 1]; }
        else { int ii = r - n_users; s = iptr[ii]; e = iptr[ii + 1]; }

        float a0 = 0.f, a1 = 0.f, a2 = 0.f, a3 = 0.f,
              a4 = 0.f, a5 = 0.f, a6 = 0.f, a7 = 0.f;
        int iters = (e - s + 3) >> 2;            // warp-uniform
        int idx = s + egrp;
        for (int i = 0; i < iters; i += 2) {     // 2x unroll, both predicated
            GATHER_FMA(idx)
            GATHER_FMA(idx + 4)
            idx += 8;
        }
        REDUCE8()
        if (egrp == 0) {
            uint4 o;
            o.x = h22u(__floats2half2_rn(a0, a1));
            o.y = h22u(__floats2half2_rn(a2, a3));
            o.z = h22u(__floats2half2_rn(a4, a5));
            o.w = h22u(__floats2half2_rn(a6, a7));
            y[(size_t)r * 8 + chunk] = o;
        }
    }
}

// last layer + epilogue: out = (x0 + h1 + h2 + acc) * 0.25  (x0/h1/h2 fp16)
__global__ void spmm_final_kernel(const uint4* __restrict__ x,   // h2
                                  const uint4* __restrict__ x0,
                                  const uint4* __restrict__ h1,
                                  float4* __restrict__ out,
                                  const int2* __restrict__ edge,
                                  const int* __restrict__ uptr,
                                  const int* __restrict__ iptr,
                                  int n_users, int n_total) {
    int warp = (blockIdx.x * blockDim.x + threadIdx.x) >> 5;
    int lane = threadIdx.x & 31;
    int egrp = lane >> 3;
    int chunk = lane & 7;
    int r0 = warp << 2;
    if (r0 >= n_total) return;

    #pragma unroll
    for (int j = 0; j < 4; j++) {
        int r = r0 + j;
        if (r >= n_total) break;
        int s, e;
        if (r < n_users) { s = uptr[r]; e = uptr[r + 1]; }
        else { int ii = r - n_users; s = iptr[ii]; e = iptr[ii + 1]; }

        float a0 = 0.f, a1 = 0.f, a2 = 0.f, a3 = 0.f,
              a4 = 0.f, a5 = 0.f, a6 = 0.f, a7 = 0.f;
        int iters = (e - s + 3) >> 2;
        int idx = s + egrp;
        for (int i = 0; i < iters; i += 2) {
            GATHER_FMA(idx)
            GATHER_FMA(idx + 4)
            idx += 8;
        }
        REDUCE8()
        if (egrp == 0) {
            size_t hoff = (size_t)r * 8 + chunk;
            uint4 u0 = x0[hoff];
            uint4 u1 = h1[hoff];
            uint4 u2 = x[hoff];
            float2 z0 = __half22float2(u2h2(u0.x));
            float2 z1 = __half22float2(u2h2(u0.y));
            float2 z2 = __half22float2(u2h2(u0.z));
            float2 z3 = __half22float2(u2h2(u0.w));
            float2 b0 = __half22float2(u2h2(u1.x));
            float2 b1 = __half22float2(u2h2(u1.y));
            float2 b2 = __half22float2(u2h2(u1.z));
            float2 b3 = __half22float2(u2h2(u1.w));
            float2 c0 = __half22float2(u2h2(u2.x));
            float2 c1 = __half22float2(u2h2(u2.y));
            float2 c2 = __half22float2(u2h2(u2.z));
            float2 c3 = __half22float2(u2h2(u2.w));
            float4 r0v, r1v;
            r0v.x = (z0.x + b0.x + c0.x + a0) * 0.25f;
            r0v.y = (z0.y + b0.y + c0.y + a1) * 0.25f;
            r0v.z = (z1.x + b1.x + c1.x + a2) * 0.25f;
            r0v.w = (z1.y + b1.y + c1.y + a3) * 0.25f;
            r1v.x = (z2.x + b2.x + c2.x + a4) * 0.25f;
            r1v.y = (z2.y + b2.y + c2.y + a5) * 0.25f;
            r1v.z = (z3.x + b3.x + c3.x + a6) * 0.25f;
            r1v.w = (z3.y + b3.y + c3.y + a7) * 0.25f;
            size_t foff = (size_t)r * 16 + chunk * 2;
            out[foff] = r0v;
            out[foff + 1] = r1v;
        }
    }
}

extern "C" void kernel_launch(void* const* d_in, const int* in_sizes, int n_in,
                              void* d_out, int out_size) {
    const float* user_emb = (const float*)d_in[0];
    const float* item_emb = (const float*)d_in[1];
    const int*   row      = (const int*)d_in[2];
    const int*   col      = (const int*)d_in[3];
    const float* vals     = (const float*)d_in[4];

    const int n_users = in_sizes[0] / D;
    const int n_items = in_sizes[1] / D;
    const int n_total = n_users + n_items;
    const int E       = in_sizes[2];
    const int P       = E / 2;

    float* out = (float*)d_out;

    __half *x0h, *h1, *h2;
    int *u_ptr, *i_ptr, *i_work, *cnt, *bsums;
    int2 *edge;
    cudaGetSymbolAddress((void**)&x0h, g_x0);
    cudaGetSymbolAddress((void**)&h1, g_h1);
    cudaGetSymbolAddress((void**)&h2, g_h2);
    cudaGetSymbolAddress((void**)&edge, g_edge);
    cudaGetSymbolAddress((void**)&u_ptr, g_u_ptr);
    cudaGetSymbolAddress((void**)&i_ptr, g_i_ptr);
    cudaGetSymbolAddress((void**)&i_work, g_i_work);
    cudaGetSymbolAddress((void**)&cnt, g_cnt);
    cudaGetSymbolAddress((void**)&bsums, g_bsums);

    const int TB = 256;
    const int n_u4 = n_total * 8;
    const int n_user_u4 = n_users * 8;
    const int n_cnt = n_items + 1;

    // 1. init: x0h = half(x0); zero item counters
    init_kernel<<<(n_u4 + TB - 1) / TB, TB>>>(
        (const float4*)user_emb, (const float4*)item_emb,
        (uint4*)x0h, cnt, n_user_u4, n_u4, n_cnt);

    // 2. user CSR pointers
    build_uptr_kernel<<<(n_users + 1 + TB - 1) / TB, TB>>>(row, P, u_ptr, n_users);

    // 3. item degrees + pack user edges
    count_pack_kernel<<<(P + TB - 1) / TB, TB>>>(col, vals, P, cnt, edge, n_users);

    // 4. exclusive scan -> i_ptr
    int n_scan = n_cnt;
    int nb = (n_scan + SCAN_BLK - 1) / SCAN_BLK;
    scan1_kernel<<<nb, SCAN_BLK>>>(cnt, i_ptr, bsums, n_scan);
    scan2_kernel<<<1, 512>>>(bsums, nb);
    scan3_kernel<<<(n_scan + TB - 1) / TB, TB>>>(i_ptr, i_work, bsums, n_scan, P);

    // 5. scatter transpose
    scatter_kernel<<<(P + TB - 1) / TB, TB>>>(row, col, vals, P, i_work, edge, n_users);

    // 6-8. three SpMM layers (joint-row: 4 edges/warp-gather, uniform trip count)
    int nwarps = (n_total + 3) / 4;
    int spmm_blocks = (nwarps * 32 + TB - 1) / TB;
    spmm_kernel<<<spmm_blocks, TB>>>((const uint4*)x0h, (uint4*)h1,
                                     edge, u_ptr, i_ptr, n_users, n_total);
    spmm_kernel<<<spmm_blocks, TB>>>((const uint4*)h1, (uint4*)h2,
                                     edge, u_ptr, i_ptr, n_users, n_total);
    spmm_final_kernel<<<spmm_blocks, TB>>>((const uint4*)h2, (const uint4*)x0h,
                                           (const uint4*)h1, (float4*)out,
                                           edge, u_ptr, i_ptr, n_users, n_total);
}